// round 3
// baseline (speedup 1.0000x reference)
#include <cuda_runtime.h>
#include <cstddef>

// Fixed shapes
constexpr int B = 32;
constexpr int C = 256;
constexpr int H = 64;
constexpr int HW = H * H;           // 4096
constexpr int N = 2048;             // anchors per batch
constexpr int CHUNK = 8;            // channels per CTA
constexpr int NCHUNKS = C / CHUNK;  // 32
constexpr int THREADS = 1024;
constexpr int SMEM_VEC4 = HW * 2;   // 8192 float4 (pixel-major: 2 float4 per pixel)
constexpr size_t SMEM_BYTES = SMEM_VEC4 * sizeof(float4);  // 128 KB

// Swizzled float4 index for (pixel p, half h): flips bit0 based on bit2 of p
// so staging STS.128 (consecutive e) is bank-conflict-free.
__device__ __forceinline__ int sidx(int p, int h) {
    return (p * 2 + h) ^ ((p >> 2) & 1);
}

__device__ __forceinline__ float4 lerp4(float4 a, float4 b, float t) {
    return make_float4(fmaf(b.x - a.x, t, a.x),
                       fmaf(b.y - a.y, t, a.y),
                       fmaf(b.z - a.z, t, a.z),
                       fmaf(b.w - a.w, t, a.w));
}

__global__ __launch_bounds__(THREADS, 1)
void bilinear_gather_kernel(const float* __restrict__ fm,
                            const float* __restrict__ anchors,
                            float* __restrict__ out)
{
    extern __shared__ float4 s4[];   // [8192], swizzled pixel-major

    const int blk   = blockIdx.x;
    const int b     = blk >> 5;      // / NCHUNKS
    const int chunk = blk & 31;      // % NCHUNKS

    // ---- Stage + transpose: gmem (channel-major) -> smem (pixel-major).
    // e = p*2 + h; thread reads 4 coalesced scalars (one per channel), writes
    // one STS.128. Swizzle makes the stores conflict-free (verified per-phase).
    {
        const float* __restrict__ src =
            fm + ((size_t)b * C + (size_t)chunk * CHUNK) * HW;
        for (int e = threadIdx.x; e < SMEM_VEC4; e += THREADS) {
            const int p = e >> 1;
            const int cb = (e & 1) * 4;
            float4 v;
            v.x = src[(cb + 0) * HW + p];
            v.y = src[(cb + 1) * HW + p];
            v.z = src[(cb + 2) * HW + p];
            v.w = src[(cb + 3) * HW + p];
            s4[e ^ ((e >> 3) & 1)] = v;
        }
    }
    __syncthreads();

    const float2* __restrict__ anc2 =
        reinterpret_cast<const float2*>(anchors + (size_t)b * N * 2);
    float* __restrict__ outb = out + (size_t)b * N * C + (size_t)chunk * CHUNK;

    // ---- Gather: one thread per anchor (2 anchors/thread), 2x LDS.128 per corner.
    for (int n = threadIdx.x; n < N; n += THREADS) {
        float2 a = anc2[n];
        float px = fminf(fmaxf(a.x * 63.0f, 0.0f), 63.0f);
        float py = fminf(fmaxf(a.y * 63.0f, 0.0f), 63.0f);

        float fx = floorf(px), fy = floorf(py);
        float cx = ceilf(px),  cy = ceilf(py);   // matches reference (rb==lt when integral)
        int xl = (int)fx, yl = (int)fy;
        int xr = (int)cx, yr = (int)cy;
        float dx = px - fx;
        float dy = py - fy;

        int p_lt = yl * H + xl;
        int p_rt = yl * H + xr;
        int p_lb = yr * H + xl;
        int p_rb = yr * H + xr;

        float4* __restrict__ o4 = reinterpret_cast<float4*>(outb + (size_t)n * C);

        #pragma unroll
        for (int h = 0; h < 2; ++h) {
            float4 vlt = s4[sidx(p_lt, h)];
            float4 vrt = s4[sidx(p_rt, h)];
            float4 vlb = s4[sidx(p_lb, h)];
            float4 vrb = s4[sidx(p_rb, h)];
            float4 vt = lerp4(vlt, vrt, dx);
            float4 vb = lerp4(vlb, vrb, dx);
            o4[h] = lerp4(vt, vb, dy);
        }
    }
}

extern "C" void kernel_launch(void* const* d_in, const int* in_sizes, int n_in,
                              void* d_out, int out_size)
{
    const float* fm      = (const float*)d_in[0];  // (32,256,64,64) fp32
    const float* anchors = (const float*)d_in[1];  // (32,2048,2) fp32
    float* out           = (float*)d_out;          // (32,2048,256) fp32

    cudaFuncSetAttribute(bilinear_gather_kernel,
                         cudaFuncAttributeMaxDynamicSharedMemorySize,
                         (int)SMEM_BYTES);

    dim3 grid(B * NCHUNKS);   // 1024 CTAs
    dim3 block(THREADS);
    bilinear_gather_kernel<<<grid, block, SMEM_BYTES>>>(fm, anchors, out);
}

// round 6
// speedup vs baseline: 1.4316x; 1.4316x over previous
#include <cuda_runtime.h>
#include <cstddef>

// Fixed shapes
constexpr int B = 32;
constexpr int C = 256;
constexpr int H = 64;
constexpr int HW = H * H;           // 4096
constexpr int N = 2048;             // anchors per batch
constexpr int CHUNK = 4;            // channels per CTA
constexpr int NCHUNKS = C / CHUNK;  // 64
constexpr int THREADS = 512;
constexpr int SMEM_FLOATS = CHUNK * HW;          // 16384 floats
constexpr size_t SMEM_BYTES = SMEM_FLOATS * 4;   // 64 KB -> 2 CTAs/SM

__global__ __launch_bounds__(THREADS, 2)
void bilinear_gather_kernel(const float* __restrict__ fm,
                            const float* __restrict__ anchors,
                            float* __restrict__ out)
{
    extern __shared__ float s[];   // [CHUNK][HW], channel-major

    const int blk   = blockIdx.x;
    const int b     = blk >> 6;      // / NCHUNKS
    const int chunk = blk & 63;      // % NCHUNKS

    // ---- Stage (b, chunk) slice: coalesced LDG.128 -> STS.128.
    // Each fm byte is read exactly once across the grid -> HBM floor.
    {
        const float4* __restrict__ src4 =
            reinterpret_cast<const float4*>(fm + ((size_t)b * C + (size_t)chunk * CHUNK) * HW);
        float4* __restrict__ s4 = reinterpret_cast<float4*>(s);
        #pragma unroll
        for (int i = threadIdx.x; i < SMEM_FLOATS / 4; i += THREADS) {
            s4[i] = src4[i];
        }
    }
    __syncthreads();

    const float2* __restrict__ anc2 =
        reinterpret_cast<const float2*>(anchors + (size_t)b * N * 2);
    float* __restrict__ outb = out + (size_t)b * N * C + (size_t)chunk * CHUNK;

    // ---- Gather: 4 anchors per thread (independent iterations for ILP).
    for (int n = threadIdx.x; n < N; n += THREADS) {
        float2 a = anc2[n];
        float px = fminf(fmaxf(a.x * 63.0f, 0.0f), 63.0f);
        float py = fminf(fmaxf(a.y * 63.0f, 0.0f), 63.0f);

        float fx = floorf(px), fy = floorf(py);
        float cx = ceilf(px),  cy = ceilf(py);   // matches reference (rb==lt when integral)
        int xl = (int)fx, yl = (int)fy;
        int xr = (int)cx, yr = (int)cy;
        float dx = px - fx;
        float dy = py - fy;

        int i_lt = yl * H + xl;
        int i_rt = yl * H + xr;
        int i_lb = yr * H + xl;
        int i_rb = yr * H + xr;

        float res[CHUNK];
        #pragma unroll
        for (int c = 0; c < CHUNK; ++c) {
            const float* __restrict__ sc = s + c * HW;
            float vlt = sc[i_lt];
            float vrt = sc[i_rt];
            float vlb = sc[i_lb];
            float vrb = sc[i_rb];
            float vt = fmaf(vrt - vlt, dx, vlt);
            float vb = fmaf(vrb - vlb, dx, vlb);
            res[c]   = fmaf(vb - vt, dy, vt);
        }

        // 16 contiguous bytes per anchor (STG.128).
        float4* __restrict__ o4 = reinterpret_cast<float4*>(outb + (size_t)n * C);
        o4[0] = make_float4(res[0], res[1], res[2], res[3]);
    }
}

extern "C" void kernel_launch(void* const* d_in, const int* in_sizes, int n_in,
                              void* d_out, int out_size)
{
    const float* fm      = (const float*)d_in[0];  // (32,256,64,64) fp32
    const float* anchors = (const float*)d_in[1];  // (32,2048,2) fp32
    float* out           = (float*)d_out;          // (32,2048,256) fp32

    cudaFuncSetAttribute(bilinear_gather_kernel,
                         cudaFuncAttributeMaxDynamicSharedMemorySize,
                         (int)SMEM_BYTES);

    dim3 grid(B * NCHUNKS);   // 2048 CTAs
    dim3 block(THREADS);
    bilinear_gather_kernel<<<grid, block, SMEM_BYTES>>>(fm, anchors, out);
}